// round 1
// baseline (speedup 1.0000x reference)
#include <cuda_runtime.h>
#include <math.h>

#define N_SRC 100000
#define N_DST 100000
#define NE    1600000
#define DIN   128
#define DOUT  128
#define DCAT  256   // DIN + DOUT

// ---------------- scratch (static device globals; no allocs allowed) ----------------
__device__ float g_n[(size_t)N_SRC * DOUT];     // relu(h_src @ Q^T + b)
__device__ float g_agg[(size_t)N_DST * DOUT];   // segment-sum of n[src]*w
__device__ float g_ws[N_DST];                   // segment-sum of w
__device__ float g_x2[(size_t)N_DST * DCAT];    // concat(agg/ws, h_dst)

// ---------------- zero agg + ws every call (graph-replay safe) ----------------
__global__ void zero_kernel() {
    size_t i = (size_t)blockIdx.x * blockDim.x + threadIdx.x;   // float4 index
    size_t n4 = (size_t)N_DST * DOUT / 4;
    if (i < n4) {
        ((float4*)g_agg)[i] = make_float4(0.f, 0.f, 0.f, 0.f);
    }
    if (i < N_DST) g_ws[i] = 0.f;
}

// ---------------- tiled fp32 GEMM: C[M,128] = relu(A[M,K] @ B[128,K]^T + bias) -----
// BM=128, BN=128, BK=8, 256 threads, 8x8 microtile per thread.
// NORM: fuse row L2-normalization (block owns full 128-wide rows).
template<int K, bool NORM>
__global__ void __launch_bounds__(256)
gemm_bias_relu(const float* __restrict__ A,
               const float* __restrict__ B,     // [128, K] row-major (K-contig)
               const float* __restrict__ bias,  // [128]
               float* __restrict__ C, int M)
{
    __shared__ float As[8][128];
    __shared__ float Bs[8][128];

    const int t  = threadIdx.x;
    const int tx = t & 15;          // col group (0..15)
    const int ty = t >> 4;          // row group (0..15)
    const int row0 = blockIdx.x * 128;

    // load indices for global->smem tiles
    const int lm = t >> 1;          // 0..127  (row within tile)
    const int lk = (t & 1) * 4;     // 0 or 4  (k within BK)

    float acc[8][8];
    #pragma unroll
    for (int i = 0; i < 8; i++)
        #pragma unroll
        for (int j = 0; j < 8; j++) acc[i][j] = 0.f;

    for (int k0 = 0; k0 < K; k0 += 8) {
        // A tile
        {
            int gr = row0 + lm;
            float4 v = make_float4(0.f, 0.f, 0.f, 0.f);
            if (gr < M) v = *(const float4*)(A + (size_t)gr * K + k0 + lk);
            As[lk + 0][lm] = v.x; As[lk + 1][lm] = v.y;
            As[lk + 2][lm] = v.z; As[lk + 3][lm] = v.w;
        }
        // B tile (always in-bounds: N=128 exactly)
        {
            float4 v = *(const float4*)(B + (size_t)lm * K + k0 + lk);
            Bs[lk + 0][lm] = v.x; Bs[lk + 1][lm] = v.y;
            Bs[lk + 2][lm] = v.z; Bs[lk + 3][lm] = v.w;
        }
        __syncthreads();

        #pragma unroll
        for (int kk = 0; kk < 8; kk++) {
            float a[8], b[8];
            #pragma unroll
            for (int i = 0; i < 8; i++) a[i] = As[kk][ty * 8 + i];
            #pragma unroll
            for (int j = 0; j < 8; j++) b[j] = Bs[kk][tx * 8 + j];
            #pragma unroll
            for (int i = 0; i < 8; i++)
                #pragma unroll
                for (int j = 0; j < 8; j++)
                    acc[i][j] = fmaf(a[i], b[j], acc[i][j]);
        }
        __syncthreads();
    }

    // epilogue: bias + relu
    float bv[8];
    #pragma unroll
    for (int j = 0; j < 8; j++) bv[j] = bias[tx * 8 + j];
    #pragma unroll
    for (int i = 0; i < 8; i++)
        #pragma unroll
        for (int j = 0; j < 8; j++)
            acc[i][j] = fmaxf(acc[i][j] + bv[j], 0.f);

    if (NORM) {
        __shared__ float red[128][17];
        __shared__ float rinv[128];
        #pragma unroll
        for (int i = 0; i < 8; i++) {
            float s = 0.f;
            #pragma unroll
            for (int j = 0; j < 8; j++) s = fmaf(acc[i][j], acc[i][j], s);
            red[ty * 8 + i][tx] = s;
        }
        __syncthreads();
        if (t < 128) {
            float s = 0.f;
            #pragma unroll
            for (int j = 0; j < 16; j++) s += red[t][j];
            float nrm = sqrtf(s);
            rinv[t] = (nrm > 0.f) ? (1.f / nrm) : 1.f;
        }
        __syncthreads();
        #pragma unroll
        for (int i = 0; i < 8; i++) {
            int gr = row0 + ty * 8 + i;
            if (gr < M) {
                float sc = rinv[ty * 8 + i];
                float4 v0 = make_float4(acc[i][0] * sc, acc[i][1] * sc,
                                        acc[i][2] * sc, acc[i][3] * sc);
                float4 v1 = make_float4(acc[i][4] * sc, acc[i][5] * sc,
                                        acc[i][6] * sc, acc[i][7] * sc);
                *(float4*)(C + (size_t)gr * 128 + tx * 8 + 0) = v0;
                *(float4*)(C + (size_t)gr * 128 + tx * 8 + 4) = v1;
            }
        }
    } else {
        #pragma unroll
        for (int i = 0; i < 8; i++) {
            int gr = row0 + ty * 8 + i;
            if (gr < M) {
                float4 v0 = make_float4(acc[i][0], acc[i][1], acc[i][2], acc[i][3]);
                float4 v1 = make_float4(acc[i][4], acc[i][5], acc[i][6], acc[i][7]);
                *(float4*)(C + (size_t)gr * 128 + tx * 8 + 0) = v0;
                *(float4*)(C + (size_t)gr * 128 + tx * 8 + 4) = v1;
            }
        }
    }
}

// ---------------- edge scatter: warp per edge, atomics into agg/ws ----------------
__global__ void __launch_bounds__(256)
scatter_kernel(const float* __restrict__ w,
               const int* __restrict__ src,
               const int* __restrict__ dst)
{
    int e = blockIdx.x * 8 + (threadIdx.x >> 5);
    if (e >= NE) return;
    int lane = threadIdx.x & 31;
    int s = src[e], d = dst[e];
    float wt = __ldg(w + e);
    float4 v = ((const float4*)(g_n + (size_t)s * 128))[lane];
    float* ap = g_agg + (size_t)d * 128 + lane * 4;
    atomicAdd(ap + 0, v.x * wt);
    atomicAdd(ap + 1, v.y * wt);
    atomicAdd(ap + 2, v.z * wt);
    atomicAdd(ap + 3, v.w * wt);
    if (lane == 0) atomicAdd(g_ws + d, wt);
}

// ---------------- build concat input: x2 = [agg/max(ws,1), h_dst] ----------------
__global__ void __launch_bounds__(256)
finalize_kernel(const float* __restrict__ h_dst)
{
    size_t i = (size_t)blockIdx.x * blockDim.x + threadIdx.x;  // float4 index
    size_t n4 = (size_t)N_DST * 32;                            // 32 float4 per row
    if (i >= n4) return;
    size_t r = i >> 5;
    int    q = (int)(i & 31);
    float inv = 1.f / fmaxf(g_ws[r], 1.f);
    float4 a = ((const float4*)(g_agg + r * 128))[q];
    a.x *= inv; a.y *= inv; a.z *= inv; a.w *= inv;
    ((float4*)(g_x2 + r * 256))[q] = a;
    float4 h = ((const float4*)(h_dst + r * 128))[q];
    ((float4*)(g_x2 + r * 256 + 128))[q] = h;
}

// gemm variants that read/write the device-global scratch directly
__global__ void __launch_bounds__(256)
gemm1_entry(const float* __restrict__ A, const float* __restrict__ B,
            const float* __restrict__ bias) {
    // never called; placeholder removed
}

extern "C" void kernel_launch(void* const* d_in, const int* in_sizes, int n_in,
                              void* d_out, int out_size)
{
    const float* h_src   = (const float*)d_in[0];
    const float* h_dst   = (const float*)d_in[1];
    const float* weights = (const float*)d_in[2];
    const float* Qw      = (const float*)d_in[3];
    const float* Qb      = (const float*)d_in[4];
    const float* Ww      = (const float*)d_in[5];
    const float* Wb      = (const float*)d_in[6];
    const int*   src     = (const int*)d_in[7];
    const int*   dst     = (const int*)d_in[8];
    float*       out     = (float*)d_out;

    // resolve scratch addresses (host API, not a stream op — capture-safe)
    static float *p_n = nullptr, *p_agg = nullptr, *p_x2 = nullptr;
    if (!p_n) {
        cudaGetSymbolAddress((void**)&p_n,   g_n);
        cudaGetSymbolAddress((void**)&p_agg, g_agg);
        cudaGetSymbolAddress((void**)&p_x2,  g_x2);
    }

    // 1) zero accumulators
    {
        size_t n4 = (size_t)N_DST * DOUT / 4;
        int blocks = (int)((n4 + 255) / 256);
        zero_kernel<<<blocks, 256>>>();
    }
    // 2) n = relu(h_src @ Q^T + Qb)
    gemm_bias_relu<128, false><<<(N_SRC + 127) / 128, 256>>>(h_src, Qw, Qb, p_n, N_SRC);
    // 3) edge scatter
    scatter_kernel<<<(NE + 7) / 8, 256>>>(weights, src, dst);
    // 4) build concat input
    {
        size_t n4 = (size_t)N_DST * 32;
        finalize_kernel<<<(int)((n4 + 255) / 256), 256>>>(h_dst);
    }
    // 5) out = L2norm(relu(x2 @ W^T + Wb))
    gemm_bias_relu<256, true><<<(N_DST + 127) / 128, 256>>>(p_x2, Ww, Wb, out, N_DST);
}

// round 2
// speedup vs baseline: 1.5335x; 1.5335x over previous
#include <cuda_runtime.h>
#include <math.h>

#define N_SRC 100000
#define N_DST 100000
#define NE    1600000
#define DIN   128
#define DOUT  128

// ---------------- scratch (static device globals; no allocs allowed) ----------------
__device__ float g_n[(size_t)N_SRC * DOUT];     // relu(h_src @ Q^T + b)
__device__ float g_agg[(size_t)N_DST * DOUT];   // segment-sum of n[src]*w
__device__ float g_ws[N_DST];                   // segment-sum of w

// ---------------- tiled fp32 GEMM1: C[M,128] = relu(A[M,K] @ B[128,K]^T + bias) ----
// BM=128, BN=128, BK=8, 256 threads, 8x8 microtile per thread.
__global__ void __launch_bounds__(256)
gemm_bias_relu(const float* __restrict__ A,
               const float* __restrict__ B,     // [128, 128] row-major (K-contig)
               const float* __restrict__ bias,  // [128]
               float* __restrict__ C, int M)
{
    const int K = 128;
    __shared__ float As[8][128];
    __shared__ float Bs[8][128];

    const int t  = threadIdx.x;
    const int tx = t & 15;
    const int ty = t >> 4;
    const int row0 = blockIdx.x * 128;

    const int lm = t >> 1;
    const int lk = (t & 1) * 4;

    float acc[8][8];
    #pragma unroll
    for (int i = 0; i < 8; i++)
        #pragma unroll
        for (int j = 0; j < 8; j++) acc[i][j] = 0.f;

    for (int k0 = 0; k0 < K; k0 += 8) {
        {
            int gr = row0 + lm;
            float4 v = make_float4(0.f, 0.f, 0.f, 0.f);
            if (gr < M) v = *(const float4*)(A + (size_t)gr * K + k0 + lk);
            As[lk + 0][lm] = v.x; As[lk + 1][lm] = v.y;
            As[lk + 2][lm] = v.z; As[lk + 3][lm] = v.w;
        }
        {
            float4 v = *(const float4*)(B + (size_t)lm * K + k0 + lk);
            Bs[lk + 0][lm] = v.x; Bs[lk + 1][lm] = v.y;
            Bs[lk + 2][lm] = v.z; Bs[lk + 3][lm] = v.w;
        }
        __syncthreads();

        #pragma unroll
        for (int kk = 0; kk < 8; kk++) {
            float a[8], b[8];
            #pragma unroll
            for (int i = 0; i < 8; i++) a[i] = As[kk][ty * 8 + i];
            #pragma unroll
            for (int j = 0; j < 8; j++) b[j] = Bs[kk][tx * 8 + j];
            #pragma unroll
            for (int i = 0; i < 8; i++)
                #pragma unroll
                for (int j = 0; j < 8; j++)
                    acc[i][j] = fmaf(a[i], b[j], acc[i][j]);
        }
        __syncthreads();
    }

    float bv[8];
    #pragma unroll
    for (int j = 0; j < 8; j++) bv[j] = bias[tx * 8 + j];
    #pragma unroll
    for (int i = 0; i < 8; i++)
        #pragma unroll
        for (int j = 0; j < 8; j++)
            acc[i][j] = fmaxf(acc[i][j] + bv[j], 0.f);

    #pragma unroll
    for (int i = 0; i < 8; i++) {
        int gr = row0 + ty * 8 + i;
        if (gr < M) {
            float4 v0 = make_float4(acc[i][0], acc[i][1], acc[i][2], acc[i][3]);
            float4 v1 = make_float4(acc[i][4], acc[i][5], acc[i][6], acc[i][7]);
            *(float4*)(C + (size_t)gr * 128 + tx * 8 + 0) = v0;
            *(float4*)(C + (size_t)gr * 128 + tx * 8 + 4) = v1;
        }
    }
}

// ---------------- GEMM2 fused: out = L2norm(relu([agg/max(ws,1) , h_dst] @ W^T + b))
// A is synthesized on the fly: k<128 -> agg[row][k] * inv_ws[row]; k>=128 -> h_dst.
__global__ void __launch_bounds__(256)
gemm2_fused(const float* __restrict__ agg,
            const float* __restrict__ ws,
            const float* __restrict__ hdst,
            const float* __restrict__ B,     // [128, 256] row-major
            const float* __restrict__ bias,  // [128]
            float* __restrict__ C, int M)
{
    const int K = 256;
    __shared__ float As[8][128];
    __shared__ float Bs[8][128];
    __shared__ float wsi[128];

    const int t  = threadIdx.x;
    const int tx = t & 15;
    const int ty = t >> 4;
    const int row0 = blockIdx.x * 128;

    const int lm = t >> 1;
    const int lk = (t & 1) * 4;

    if (t < 128) {
        int gr = row0 + t;
        float w = (gr < M) ? ws[gr] : 1.f;
        wsi[t] = 1.f / fmaxf(w, 1.f);
    }
    __syncthreads();

    float acc[8][8];
    #pragma unroll
    for (int i = 0; i < 8; i++)
        #pragma unroll
        for (int j = 0; j < 8; j++) acc[i][j] = 0.f;

    for (int k0 = 0; k0 < K; k0 += 8) {
        {
            int gr = row0 + lm;
            int k  = k0 + lk;
            float4 v = make_float4(0.f, 0.f, 0.f, 0.f);
            if (gr < M) {
                if (k < 128) {
                    v = *(const float4*)(agg + (size_t)gr * 128 + k);
                    float inv = wsi[lm];
                    v.x *= inv; v.y *= inv; v.z *= inv; v.w *= inv;
                } else {
                    v = *(const float4*)(hdst + (size_t)gr * 128 + (k - 128));
                }
            }
            As[lk + 0][lm] = v.x; As[lk + 1][lm] = v.y;
            As[lk + 2][lm] = v.z; As[lk + 3][lm] = v.w;
        }
        {
            float4 v = *(const float4*)(B + (size_t)lm * K + k0 + lk);
            Bs[lk + 0][lm] = v.x; Bs[lk + 1][lm] = v.y;
            Bs[lk + 2][lm] = v.z; Bs[lk + 3][lm] = v.w;
        }
        __syncthreads();

        #pragma unroll
        for (int kk = 0; kk < 8; kk++) {
            float a[8], b[8];
            #pragma unroll
            for (int i = 0; i < 8; i++) a[i] = As[kk][ty * 8 + i];
            #pragma unroll
            for (int j = 0; j < 8; j++) b[j] = Bs[kk][tx * 8 + j];
            #pragma unroll
            for (int i = 0; i < 8; i++)
                #pragma unroll
                for (int j = 0; j < 8; j++)
                    acc[i][j] = fmaf(a[i], b[j], acc[i][j]);
        }
        __syncthreads();
    }

    float bv[8];
    #pragma unroll
    for (int j = 0; j < 8; j++) bv[j] = bias[tx * 8 + j];
    #pragma unroll
    for (int i = 0; i < 8; i++)
        #pragma unroll
        for (int j = 0; j < 8; j++)
            acc[i][j] = fmaxf(acc[i][j] + bv[j], 0.f);

    // fused row L2 norm (block owns full 128-wide rows)
    __shared__ float red[128][17];
    __shared__ float rinv[128];
    #pragma unroll
    for (int i = 0; i < 8; i++) {
        float s = 0.f;
        #pragma unroll
        for (int j = 0; j < 8; j++) s = fmaf(acc[i][j], acc[i][j], s);
        red[ty * 8 + i][tx] = s;
    }
    __syncthreads();
    if (t < 128) {
        float s = 0.f;
        #pragma unroll
        for (int j = 0; j < 16; j++) s += red[t][j];
        float nrm = sqrtf(s);
        rinv[t] = (nrm > 0.f) ? (1.f / nrm) : 1.f;
    }
    __syncthreads();
    #pragma unroll
    for (int i = 0; i < 8; i++) {
        int gr = row0 + ty * 8 + i;
        if (gr < M) {
            float sc = rinv[ty * 8 + i];
            float4 v0 = make_float4(acc[i][0] * sc, acc[i][1] * sc,
                                    acc[i][2] * sc, acc[i][3] * sc);
            float4 v1 = make_float4(acc[i][4] * sc, acc[i][5] * sc,
                                    acc[i][6] * sc, acc[i][7] * sc);
            *(float4*)(C + (size_t)gr * 128 + tx * 8 + 0) = v0;
            *(float4*)(C + (size_t)gr * 128 + tx * 8 + 4) = v1;
        }
    }
}

// ---------------- edge scatter: warp per edge, vector red into agg ----------------
__global__ void __launch_bounds__(256)
scatter_kernel(const float* __restrict__ w,
               const int* __restrict__ src,
               const int* __restrict__ dst)
{
    int e = blockIdx.x * 8 + (threadIdx.x >> 5);
    if (e >= NE) return;
    int lane = threadIdx.x & 31;
    int s = src[e], d = dst[e];
    float wt = __ldg(w + e);
    float4 v = ((const float4*)(g_n + (size_t)s * 128))[lane];
    float* ap = g_agg + (size_t)d * 128 + lane * 4;
    asm volatile("red.global.add.v4.f32 [%0], {%1, %2, %3, %4};"
                 :: "l"(ap), "f"(v.x * wt), "f"(v.y * wt),
                    "f"(v.z * wt), "f"(v.w * wt)
                 : "memory");
    if (lane == 0) atomicAdd(g_ws + d, wt);
}

extern "C" void kernel_launch(void* const* d_in, const int* in_sizes, int n_in,
                              void* d_out, int out_size)
{
    const float* h_src   = (const float*)d_in[0];
    const float* h_dst   = (const float*)d_in[1];
    const float* weights = (const float*)d_in[2];
    const float* Qw      = (const float*)d_in[3];
    const float* Qb      = (const float*)d_in[4];
    const float* Ww      = (const float*)d_in[5];
    const float* Wb      = (const float*)d_in[6];
    const int*   src     = (const int*)d_in[7];
    const int*   dst     = (const int*)d_in[8];
    float*       out     = (float*)d_out;

    static float *p_n = nullptr, *p_agg = nullptr, *p_ws = nullptr;
    if (!p_n) {
        cudaGetSymbolAddress((void**)&p_n,   g_n);
        cudaGetSymbolAddress((void**)&p_agg, g_agg);
        cudaGetSymbolAddress((void**)&p_ws,  g_ws);
    }

    // 1) zero accumulators (stream memsets are graph-capturable)
    cudaMemsetAsync(p_agg, 0, (size_t)N_DST * DOUT * sizeof(float));
    cudaMemsetAsync(p_ws,  0, (size_t)N_DST * sizeof(float));

    // 2) n = relu(h_src @ Q^T + Qb)
    gemm_bias_relu<<<(N_SRC + 127) / 128, 256>>>(h_src, Qw, Qb, p_n, N_SRC);

    // 3) edge scatter (vector reductions)
    scatter_kernel<<<(NE + 7) / 8, 256>>>(weights, src, dst);

    // 4) out = L2norm(relu([agg/ws , h_dst] @ W^T + Wb))  (finalize fused in)
    gemm2_fused<<<(N_DST + 127) / 128, 256>>>(p_agg, p_ws, h_dst, Ww, Wb, out, N_DST);
}

// round 3
// speedup vs baseline: 2.1760x; 1.4190x over previous
#include <cuda_runtime.h>
#include <math.h>
#include <stdint.h>

#define N_SRC 100000
#define N_DST 100000
#define NE    1600000
#define DIN   128
#define DOUT  128

// ---------------- scratch (static device globals; no allocs allowed) ----------------
__device__ float g_n[(size_t)N_SRC * DOUT];     // relu(h_src @ Q^T + b)
__device__ float g_agg[(size_t)N_DST * DOUT];   // segment-sum of n[src]*w
__device__ float g_ws[N_DST];                   // segment-sum of w

// ---------------- tf32 helpers ----------------
__device__ __forceinline__ uint32_t f2tf32(float x) {
    uint32_t u;
    asm("cvt.rna.tf32.f32 %0, %1;" : "=r"(u) : "f"(x));
    return u;
}

__device__ __forceinline__ void mma_tf32(float* d, const uint32_t* a,
                                         const uint32_t* b, const float* c) {
    asm volatile(
        "mma.sync.aligned.m16n8k8.row.col.f32.tf32.tf32.f32 "
        "{%0,%1,%2,%3}, {%4,%5,%6,%7}, {%8,%9}, {%10,%11,%12,%13};\n"
        : "=f"(d[0]), "=f"(d[1]), "=f"(d[2]), "=f"(d[3])
        : "r"(a[0]), "r"(a[1]), "r"(a[2]), "r"(a[3]),
          "r"(b[0]), "r"(b[1]),
          "f"(c[0]), "f"(c[1]), "f"(c[2]), "f"(c[3]));
}

// ---------------- tensor-core GEMM: C[M,128] = relu(A[M,K] @ B[128,K]^T + bias) ----
// 128x128 block tile, 8 warps (4Mx2N), warp tile 32x64, K chunked by 32.
// FUSE: A synthesized as [agg*inv_ws | h_dst].  NORM: fused row L2 norm.
template<int K, bool FUSE, bool NORM>
__global__ void __launch_bounds__(256)
gemm_tc(const float* __restrict__ A,      // FUSE: agg
        const float* __restrict__ ws,
        const float* __restrict__ hdst,
        const float* __restrict__ B,      // [128, K] row-major
        const float* __restrict__ bias,   // [128]
        float* __restrict__ C, int M)
{
    __shared__ uint32_t As[128][36];
    __shared__ uint32_t Bs[128][36];
    __shared__ float wsi[128];
    __shared__ float rowsq[128];
    __shared__ float rinv[128];

    const int t     = threadIdx.x;
    const int lane  = t & 31;
    const int w     = t >> 5;
    const int warpM = w >> 1;      // 0..3
    const int warpN = w & 1;       // 0..1
    const int row0  = blockIdx.x * 128;
    const int gid   = lane >> 2;   // groupID
    const int tig   = lane & 3;    // thread in group

    if (FUSE) {
        if (t < 128) {
            int gr = row0 + t;
            float v = (gr < M) ? ws[t + row0] : 1.f;
            wsi[t] = 1.f / fmaxf(v, 1.f);
        }
        __syncthreads();
    }

    float acc[2][8][4];
    #pragma unroll
    for (int mt = 0; mt < 2; mt++)
        #pragma unroll
        for (int nt = 0; nt < 8; nt++)
            #pragma unroll
            for (int r = 0; r < 4; r++) acc[mt][nt][r] = 0.f;

    for (int k0 = 0; k0 < K; k0 += 32) {
        // ---- stage A and B chunks (convert to tf32) ----
        #pragma unroll
        for (int i = 0; i < 4; i++) {
            int lin = t + i * 256;        // 0..1023
            int row = lin >> 3;           // 0..127
            int q   = lin & 7;            // float4 slot
            int kk  = k0 + q * 4;

            float4 va = make_float4(0.f, 0.f, 0.f, 0.f);
            int gr = row0 + row;
            if (gr < M) {
                if (FUSE) {
                    if (kk < 128) {
                        va = *(const float4*)(A + (size_t)gr * 128 + kk);
                        float inv = wsi[row];
                        va.x *= inv; va.y *= inv; va.z *= inv; va.w *= inv;
                    } else {
                        va = *(const float4*)(hdst + (size_t)gr * 128 + (kk - 128));
                    }
                } else {
                    va = *(const float4*)(A + (size_t)gr * K + kk);
                }
            }
            As[row][q * 4 + 0] = f2tf32(va.x);
            As[row][q * 4 + 1] = f2tf32(va.y);
            As[row][q * 4 + 2] = f2tf32(va.z);
            As[row][q * 4 + 3] = f2tf32(va.w);

            float4 vb = *(const float4*)(B + (size_t)row * K + kk);
            Bs[row][q * 4 + 0] = f2tf32(vb.x);
            Bs[row][q * 4 + 1] = f2tf32(vb.y);
            Bs[row][q * 4 + 2] = f2tf32(vb.z);
            Bs[row][q * 4 + 3] = f2tf32(vb.w);
        }
        __syncthreads();

        // ---- 4 k-steps of 8 ----
        #pragma unroll
        for (int ks = 0; ks < 4; ks++) {
            const int kk = ks * 8;
            uint32_t a[2][4], b[8][2];
            #pragma unroll
            for (int mt = 0; mt < 2; mt++) {
                int r = warpM * 32 + mt * 16 + gid;
                a[mt][0] = As[r][kk + tig];
                a[mt][1] = As[r + 8][kk + tig];
                a[mt][2] = As[r][kk + tig + 4];
                a[mt][3] = As[r + 8][kk + tig + 4];
            }
            #pragma unroll
            for (int nt = 0; nt < 8; nt++) {
                int n = warpN * 64 + nt * 8 + gid;
                b[nt][0] = Bs[n][kk + tig];
                b[nt][1] = Bs[n][kk + tig + 4];
            }
            #pragma unroll
            for (int mt = 0; mt < 2; mt++)
                #pragma unroll
                for (int nt = 0; nt < 8; nt++)
                    mma_tf32(acc[mt][nt], a[mt], b[nt], acc[mt][nt]);
        }
        __syncthreads();
    }

    // ---- epilogue: bias + relu ----
    #pragma unroll
    for (int nt = 0; nt < 8; nt++) {
        int cb = warpN * 64 + nt * 8 + 2 * tig;
        float b0 = __ldg(bias + cb);
        float b1 = __ldg(bias + cb + 1);
        #pragma unroll
        for (int mt = 0; mt < 2; mt++) {
            acc[mt][nt][0] = fmaxf(acc[mt][nt][0] + b0, 0.f);
            acc[mt][nt][1] = fmaxf(acc[mt][nt][1] + b1, 0.f);
            acc[mt][nt][2] = fmaxf(acc[mt][nt][2] + b0, 0.f);
            acc[mt][nt][3] = fmaxf(acc[mt][nt][3] + b1, 0.f);
        }
    }

    if (NORM) {
        if (t < 128) rowsq[t] = 0.f;
        __syncthreads();
        #pragma unroll
        for (int mt = 0; mt < 2; mt++) {
            float sA = 0.f, sB = 0.f;
            #pragma unroll
            for (int nt = 0; nt < 8; nt++) {
                sA = fmaf(acc[mt][nt][0], acc[mt][nt][0], sA);
                sA = fmaf(acc[mt][nt][1], acc[mt][nt][1], sA);
                sB = fmaf(acc[mt][nt][2], acc[mt][nt][2], sB);
                sB = fmaf(acc[mt][nt][3], acc[mt][nt][3], sB);
            }
            sA += __shfl_xor_sync(0xffffffffu, sA, 1);
            sA += __shfl_xor_sync(0xffffffffu, sA, 2);
            sB += __shfl_xor_sync(0xffffffffu, sB, 1);
            sB += __shfl_xor_sync(0xffffffffu, sB, 2);
            if (tig == 0) {
                int lr = warpM * 32 + mt * 16 + gid;
                atomicAdd(&rowsq[lr], sA);
                atomicAdd(&rowsq[lr + 8], sB);
            }
        }
        __syncthreads();
        if (t < 128) {
            float nrm = sqrtf(rowsq[t]);
            rinv[t] = (nrm > 0.f) ? (1.f / nrm) : 1.f;
        }
        __syncthreads();
        #pragma unroll
        for (int mt = 0; mt < 2; mt++) {
            int lrA = warpM * 32 + mt * 16 + gid;
            int rA  = row0 + lrA;
            float sa = rinv[lrA];
            float sb = rinv[lrA + 8];
            #pragma unroll
            for (int nt = 0; nt < 8; nt++) {
                int cb = warpN * 64 + nt * 8 + 2 * tig;
                if (rA < M) {
                    float2 v = make_float2(acc[mt][nt][0] * sa, acc[mt][nt][1] * sa);
                    *(float2*)(C + (size_t)rA * 128 + cb) = v;
                }
                if (rA + 8 < M) {
                    float2 v = make_float2(acc[mt][nt][2] * sb, acc[mt][nt][3] * sb);
                    *(float2*)(C + (size_t)(rA + 8) * 128 + cb) = v;
                }
            }
        }
    } else {
        #pragma unroll
        for (int mt = 0; mt < 2; mt++) {
            int rA = row0 + warpM * 32 + mt * 16 + gid;
            #pragma unroll
            for (int nt = 0; nt < 8; nt++) {
                int cb = warpN * 64 + nt * 8 + 2 * tig;
                if (rA < M) {
                    float2 v = make_float2(acc[mt][nt][0], acc[mt][nt][1]);
                    *(float2*)(C + (size_t)rA * 128 + cb) = v;
                }
                if (rA + 8 < M) {
                    float2 v = make_float2(acc[mt][nt][2], acc[mt][nt][3]);
                    *(float2*)(C + (size_t)(rA + 8) * 128 + cb) = v;
                }
            }
        }
    }
}

// ---------------- edge scatter: warp per edge, vector red into agg ----------------
__global__ void __launch_bounds__(256)
scatter_kernel(const float* __restrict__ w,
               const int* __restrict__ src,
               const int* __restrict__ dst)
{
    int e = blockIdx.x * 8 + (threadIdx.x >> 5);
    if (e >= NE) return;
    int lane = threadIdx.x & 31;
    int s = src[e], d = dst[e];
    float wt = __ldg(w + e);
    float4 v = ((const float4*)(g_n + (size_t)s * 128))[lane];
    float* ap = g_agg + (size_t)d * 128 + lane * 4;
    asm volatile("red.global.add.v4.f32 [%0], {%1, %2, %3, %4};"
                 :: "l"(ap), "f"(v.x * wt), "f"(v.y * wt),
                    "f"(v.z * wt), "f"(v.w * wt)
                 : "memory");
    if (lane == 0) atomicAdd(g_ws + d, wt);
}

extern "C" void kernel_launch(void* const* d_in, const int* in_sizes, int n_in,
                              void* d_out, int out_size)
{
    const float* h_src   = (const float*)d_in[0];
    const float* h_dst   = (const float*)d_in[1];
    const float* weights = (const float*)d_in[2];
    const float* Qw      = (const float*)d_in[3];
    const float* Qb      = (const float*)d_in[4];
    const float* Ww      = (const float*)d_in[5];
    const float* Wb      = (const float*)d_in[6];
    const int*   src     = (const int*)d_in[7];
    const int*   dst     = (const int*)d_in[8];
    float*       out     = (float*)d_out;

    static float *p_n = nullptr, *p_agg = nullptr, *p_ws = nullptr;
    if (!p_n) {
        cudaGetSymbolAddress((void**)&p_n,   g_n);
        cudaGetSymbolAddress((void**)&p_agg, g_agg);
        cudaGetSymbolAddress((void**)&p_ws,  g_ws);
    }

    // 1) zero accumulators
    cudaMemsetAsync(p_agg, 0, (size_t)N_DST * DOUT * sizeof(float));
    cudaMemsetAsync(p_ws,  0, (size_t)N_DST * sizeof(float));

    // 2) n = relu(h_src @ Q^T + Qb)   [tensor cores, tf32]
    gemm_tc<128, false, false><<<(N_SRC + 127) / 128, 256>>>(
        h_src, nullptr, nullptr, Qw, Qb, p_n, N_SRC);

    // 3) edge scatter (vector reductions)
    scatter_kernel<<<(NE + 7) / 8, 256>>>(weights, src, dst);

    // 4) out = L2norm(relu([agg/ws , h_dst] @ W^T + Wb))   [tensor cores, tf32]
    gemm_tc<256, true, true><<<(N_DST + 127) / 128, 256>>>(
        p_agg, p_ws, h_dst, Ww, Wb, out, N_DST);
}

// round 4
// speedup vs baseline: 3.2482x; 1.4927x over previous
#include <cuda_runtime.h>
#include <math.h>
#include <stdint.h>

#define N_SRC 100000
#define N_DST 100000
#define NE    1600000
#define DIN   128
#define DOUT  128

// ---------------- scratch (static device globals; no allocs allowed) ----------------
__device__ float g_n[(size_t)N_SRC * DOUT];     // relu(h_src @ Q^T + b)
__device__ float g_agg[(size_t)N_DST * DOUT];   // aggregated + normalized messages
__device__ int   g_deg[N_DST];                  // per-dst degree
__device__ int   g_off[N_DST];                  // CSR bucket start
__device__ int   g_cur[N_DST];                  // CSR cursor (== end after fill)
__device__ int   g_esrc[NE];                    // bucketed src indices
__device__ float g_ew[NE];                      // bucketed edge weights
__device__ int   g_total;                       // global scan counter

// ---------------- tf32 helpers ----------------
__device__ __forceinline__ uint32_t f2tf32(float x) {
    uint32_t u;
    asm("cvt.rna.tf32.f32 %0, %1;" : "=r"(u) : "f"(x));
    return u;
}

__device__ __forceinline__ void mma_tf32(float* d, const uint32_t* a,
                                         const uint32_t* b, const float* c) {
    asm volatile(
        "mma.sync.aligned.m16n8k8.row.col.f32.tf32.tf32.f32 "
        "{%0,%1,%2,%3}, {%4,%5,%6,%7}, {%8,%9}, {%10,%11,%12,%13};\n"
        : "=f"(d[0]), "=f"(d[1]), "=f"(d[2]), "=f"(d[3])
        : "r"(a[0]), "r"(a[1]), "r"(a[2]), "r"(a[3]),
          "r"(b[0]), "r"(b[1]),
          "f"(c[0]), "f"(c[1]), "f"(c[2]), "f"(c[3]));
}

// ---------------- tensor-core GEMM: C[M,128] = relu(A[M,K] @ B[128,K]^T + bias) ----
// 128x128 block tile, 8 warps (4Mx2N), warp tile 32x64, K chunked by 32.
// FUSE: A synthesized as [agg(prenormalized) | h_dst].  NORM: fused row L2 norm.
template<int K, bool FUSE, bool NORM>
__global__ void __launch_bounds__(256)
gemm_tc(const float* __restrict__ A,
        const float* __restrict__ hdst,
        const float* __restrict__ B,      // [128, K] row-major
        const float* __restrict__ bias,   // [128]
        float* __restrict__ C, int M)
{
    __shared__ uint32_t As[128][36];
    __shared__ uint32_t Bs[128][36];
    __shared__ float rowsq[128];
    __shared__ float rinv[128];

    const int t     = threadIdx.x;
    const int lane  = t & 31;
    const int w     = t >> 5;
    const int warpM = w >> 1;
    const int warpN = w & 1;
    const int row0  = blockIdx.x * 128;
    const int gid   = lane >> 2;
    const int tig   = lane & 3;

    float acc[2][8][4];
    #pragma unroll
    for (int mt = 0; mt < 2; mt++)
        #pragma unroll
        for (int nt = 0; nt < 8; nt++)
            #pragma unroll
            for (int r = 0; r < 4; r++) acc[mt][nt][r] = 0.f;

    for (int k0 = 0; k0 < K; k0 += 32) {
        #pragma unroll
        for (int i = 0; i < 4; i++) {
            int lin = t + i * 256;
            int row = lin >> 3;
            int q   = lin & 7;
            int kk  = k0 + q * 4;

            float4 va = make_float4(0.f, 0.f, 0.f, 0.f);
            int gr = row0 + row;
            if (gr < M) {
                if (FUSE) {
                    if (kk < 128)
                        va = *(const float4*)(A + (size_t)gr * 128 + kk);
                    else
                        va = *(const float4*)(hdst + (size_t)gr * 128 + (kk - 128));
                } else {
                    va = *(const float4*)(A + (size_t)gr * K + kk);
                }
            }
            As[row][q * 4 + 0] = f2tf32(va.x);
            As[row][q * 4 + 1] = f2tf32(va.y);
            As[row][q * 4 + 2] = f2tf32(va.z);
            As[row][q * 4 + 3] = f2tf32(va.w);

            float4 vb = *(const float4*)(B + (size_t)row * K + kk);
            Bs[row][q * 4 + 0] = f2tf32(vb.x);
            Bs[row][q * 4 + 1] = f2tf32(vb.y);
            Bs[row][q * 4 + 2] = f2tf32(vb.z);
            Bs[row][q * 4 + 3] = f2tf32(vb.w);
        }
        __syncthreads();

        #pragma unroll
        for (int ks = 0; ks < 4; ks++) {
            const int kk = ks * 8;
            uint32_t a[2][4], b[8][2];
            #pragma unroll
            for (int mt = 0; mt < 2; mt++) {
                int r = warpM * 32 + mt * 16 + gid;
                a[mt][0] = As[r][kk + tig];
                a[mt][1] = As[r + 8][kk + tig];
                a[mt][2] = As[r][kk + tig + 4];
                a[mt][3] = As[r + 8][kk + tig + 4];
            }
            #pragma unroll
            for (int nt = 0; nt < 8; nt++) {
                int n = warpN * 64 + nt * 8 + gid;
                b[nt][0] = Bs[n][kk + tig];
                b[nt][1] = Bs[n][kk + tig + 4];
            }
            #pragma unroll
            for (int mt = 0; mt < 2; mt++)
                #pragma unroll
                for (int nt = 0; nt < 8; nt++)
                    mma_tf32(acc[mt][nt], a[mt], b[nt], acc[mt][nt]);
        }
        __syncthreads();
    }

    #pragma unroll
    for (int nt = 0; nt < 8; nt++) {
        int cb = warpN * 64 + nt * 8 + 2 * tig;
        float b0 = __ldg(bias + cb);
        float b1 = __ldg(bias + cb + 1);
        #pragma unroll
        for (int mt = 0; mt < 2; mt++) {
            acc[mt][nt][0] = fmaxf(acc[mt][nt][0] + b0, 0.f);
            acc[mt][nt][1] = fmaxf(acc[mt][nt][1] + b1, 0.f);
            acc[mt][nt][2] = fmaxf(acc[mt][nt][2] + b0, 0.f);
            acc[mt][nt][3] = fmaxf(acc[mt][nt][3] + b1, 0.f);
        }
    }

    if (NORM) {
        if (t < 128) rowsq[t] = 0.f;
        __syncthreads();
        #pragma unroll
        for (int mt = 0; mt < 2; mt++) {
            float sA = 0.f, sB = 0.f;
            #pragma unroll
            for (int nt = 0; nt < 8; nt++) {
                sA = fmaf(acc[mt][nt][0], acc[mt][nt][0], sA);
                sA = fmaf(acc[mt][nt][1], acc[mt][nt][1], sA);
                sB = fmaf(acc[mt][nt][2], acc[mt][nt][2], sB);
                sB = fmaf(acc[mt][nt][3], acc[mt][nt][3], sB);
            }
            sA += __shfl_xor_sync(0xffffffffu, sA, 1);
            sA += __shfl_xor_sync(0xffffffffu, sA, 2);
            sB += __shfl_xor_sync(0xffffffffu, sB, 1);
            sB += __shfl_xor_sync(0xffffffffu, sB, 2);
            if (tig == 0) {
                int lr = warpM * 32 + mt * 16 + gid;
                atomicAdd(&rowsq[lr], sA);
                atomicAdd(&rowsq[lr + 8], sB);
            }
        }
        __syncthreads();
        if (t < 128) {
            float nrm = sqrtf(rowsq[t]);
            rinv[t] = (nrm > 0.f) ? (1.f / nrm) : 1.f;
        }
        __syncthreads();
        #pragma unroll
        for (int mt = 0; mt < 2; mt++) {
            int lrA = warpM * 32 + mt * 16 + gid;
            int rA  = row0 + lrA;
            float sa = rinv[lrA];
            float sb = rinv[lrA + 8];
            #pragma unroll
            for (int nt = 0; nt < 8; nt++) {
                int cb = warpN * 64 + nt * 8 + 2 * tig;
                if (rA < M) {
                    float2 v = make_float2(acc[mt][nt][0] * sa, acc[mt][nt][1] * sa);
                    *(float2*)(C + (size_t)rA * 128 + cb) = v;
                }
                if (rA + 8 < M) {
                    float2 v = make_float2(acc[mt][nt][2] * sb, acc[mt][nt][3] * sb);
                    *(float2*)(C + (size_t)(rA + 8) * 128 + cb) = v;
                }
            }
        }
    } else {
        #pragma unroll
        for (int mt = 0; mt < 2; mt++) {
            int rA = row0 + warpM * 32 + mt * 16 + gid;
            #pragma unroll
            for (int nt = 0; nt < 8; nt++) {
                int cb = warpN * 64 + nt * 8 + 2 * tig;
                if (rA < M) {
                    float2 v = make_float2(acc[mt][nt][0], acc[mt][nt][1]);
                    *(float2*)(C + (size_t)rA * 128 + cb) = v;
                }
                if (rA + 8 < M) {
                    float2 v = make_float2(acc[mt][nt][2], acc[mt][nt][3]);
                    *(float2*)(C + (size_t)(rA + 8) * 128 + cb) = v;
                }
            }
        }
    }
}

// ---------------- CSR build ----------------
__global__ void __launch_bounds__(256)
hist_kernel(const int* __restrict__ dst)
{
    int e = blockIdx.x * 256 + threadIdx.x;
    if (e < NE) atomicAdd(&g_deg[dst[e]], 1);
}

// per-block exclusive scan; block base via one global atomicAdd (order-arbitrary,
// valid disjoint partition of [0, NE))
__global__ void __launch_bounds__(256)
scan_kernel()
{
    __shared__ int s[256];
    __shared__ int base;
    int d = blockIdx.x * 256 + threadIdx.x;
    int t = threadIdx.x;
    int deg = (d < N_DST) ? g_deg[d] : 0;
    s[t] = deg;
    __syncthreads();
    #pragma unroll
    for (int o = 1; o < 256; o <<= 1) {
        int v = (t >= o) ? s[t - o] : 0;
        __syncthreads();
        s[t] += v;
        __syncthreads();
    }
    if (t == 255) base = atomicAdd(&g_total, s[255]);
    __syncthreads();
    if (d < N_DST) {
        int off = base + s[t] - deg;   // exclusive
        g_off[d] = off;
        g_cur[d] = off;
    }
}

__global__ void __launch_bounds__(256)
bucket_kernel(const int* __restrict__ src,
              const int* __restrict__ dst,
              const float* __restrict__ w)
{
    int e = blockIdx.x * 256 + threadIdx.x;
    if (e >= NE) return;
    int d = dst[e];
    int pos = atomicAdd(&g_cur[d], 1);
    g_esrc[pos] = src[e];
    g_ew[pos]   = w[e];
}

// ---------------- aggregation: warp per dst node, no atomics --------------------
__global__ void __launch_bounds__(256)
aggregate_kernel()
{
    int d = blockIdx.x * 8 + (threadIdx.x >> 5);
    if (d >= N_DST) return;
    int lane = threadIdx.x & 31;
    int beg = g_off[d];
    int end = g_cur[d];   // == off + deg after bucket fill

    float4 acc = make_float4(0.f, 0.f, 0.f, 0.f);
    float ws = 0.f;
    int i = beg;
    // 2-wide software pipeline for MLP
    for (; i + 1 < end; i += 2) {
        int   s0 = g_esrc[i],     s1 = g_esrc[i + 1];
        float w0 = g_ew[i],       w1 = g_ew[i + 1];
        float4 v0 = ((const float4*)(g_n + (size_t)s0 * 128))[lane];
        float4 v1 = ((const float4*)(g_n + (size_t)s1 * 128))[lane];
        acc.x = fmaf(v0.x, w0, acc.x); acc.y = fmaf(v0.y, w0, acc.y);
        acc.z = fmaf(v0.z, w0, acc.z); acc.w = fmaf(v0.w, w0, acc.w);
        acc.x = fmaf(v1.x, w1, acc.x); acc.y = fmaf(v1.y, w1, acc.y);
        acc.z = fmaf(v1.z, w1, acc.z); acc.w = fmaf(v1.w, w1, acc.w);
        ws += w0 + w1;
    }
    if (i < end) {
        int s0 = g_esrc[i];
        float w0 = g_ew[i];
        float4 v0 = ((const float4*)(g_n + (size_t)s0 * 128))[lane];
        acc.x = fmaf(v0.x, w0, acc.x); acc.y = fmaf(v0.y, w0, acc.y);
        acc.z = fmaf(v0.z, w0, acc.z); acc.w = fmaf(v0.w, w0, acc.w);
        ws += w0;
    }
    float inv = 1.f / fmaxf(ws, 1.f);
    acc.x *= inv; acc.y *= inv; acc.z *= inv; acc.w *= inv;
    ((float4*)(g_agg + (size_t)d * 128))[lane] = acc;
}

extern "C" void kernel_launch(void* const* d_in, const int* in_sizes, int n_in,
                              void* d_out, int out_size)
{
    const float* h_src   = (const float*)d_in[0];
    const float* h_dst   = (const float*)d_in[1];
    const float* weights = (const float*)d_in[2];
    const float* Qw      = (const float*)d_in[3];
    const float* Qb      = (const float*)d_in[4];
    const float* Ww      = (const float*)d_in[5];
    const float* Wb      = (const float*)d_in[6];
    const int*   src     = (const int*)d_in[7];
    const int*   dst     = (const int*)d_in[8];
    float*       out     = (float*)d_out;

    static float *p_n = nullptr, *p_agg = nullptr;
    static int   *p_deg = nullptr, *p_total = nullptr;
    if (!p_n) {
        cudaGetSymbolAddress((void**)&p_n,     g_n);
        cudaGetSymbolAddress((void**)&p_agg,   g_agg);
        cudaGetSymbolAddress((void**)&p_deg,   g_deg);
        cudaGetSymbolAddress((void**)&p_total, g_total);
    }

    // 0) reset CSR counters
    cudaMemsetAsync(p_deg,   0, N_DST * sizeof(int));
    cudaMemsetAsync(p_total, 0, sizeof(int));

    // 1) n = relu(h_src @ Q^T + Qb)   [tf32 tensor cores]
    gemm_tc<128, false, false><<<(N_SRC + 127) / 128, 256>>>(
        h_src, nullptr, Qw, Qb, p_n, N_SRC);

    // 2) CSR build
    hist_kernel<<<(NE + 255) / 256, 256>>>(dst);
    scan_kernel<<<(N_DST + 255) / 256, 256>>>();
    bucket_kernel<<<(NE + 255) / 256, 256>>>(src, dst, weights);

    // 3) aggregate (atomic-free, pre-normalized)
    aggregate_kernel<<<(N_DST + 7) / 8, 256>>>();

    // 4) out = L2norm(relu([agg , h_dst] @ W^T + Wb))   [tf32 tensor cores]
    gemm_tc<256, true, true><<<(N_DST + 127) / 128, 256>>>(
        p_agg, h_dst, Ww, Wb, out, N_DST);
}

// round 5
// speedup vs baseline: 3.5937x; 1.1063x over previous
#include <cuda_runtime.h>
#include <cuda_fp16.h>
#include <math.h>
#include <stdint.h>

#define N_SRC 100000
#define N_DST 100000
#define NE    1600000
#define DIN   128
#define DOUT  128

// ---------------- scratch (static device globals; no allocs allowed) ----------------
__device__ __half    g_nh[(size_t)N_SRC * DOUT];  // relu(h_src @ Q^T + b), fp16
__device__ float     g_agg[(size_t)N_DST * DOUT]; // aggregated + normalized messages
__device__ int       g_deg[N_DST];                // per-dst degree
__device__ int       g_off[N_DST];                // CSR bucket start
__device__ int       g_cur[N_DST];                // CSR cursor (== end after fill)
__device__ uint64_t  g_edge[NE];                  // packed (src:int32 lo, w:f32 hi)
__device__ int       g_total;                     // global scan counter

// ---------------- tf32 helpers ----------------
__device__ __forceinline__ uint32_t f2tf32(float x) {
    uint32_t u;
    asm("cvt.rna.tf32.f32 %0, %1;" : "=r"(u) : "f"(x));
    return u;
}

__device__ __forceinline__ void mma_tf32(float* d, const uint32_t* a,
                                         const uint32_t* b, const float* c) {
    asm volatile(
        "mma.sync.aligned.m16n8k8.row.col.f32.tf32.tf32.f32 "
        "{%0,%1,%2,%3}, {%4,%5,%6,%7}, {%8,%9}, {%10,%11,%12,%13};\n"
        : "=f"(d[0]), "=f"(d[1]), "=f"(d[2]), "=f"(d[3])
        : "r"(a[0]), "r"(a[1]), "r"(a[2]), "r"(a[3]),
          "r"(b[0]), "r"(b[1]),
          "f"(c[0]), "f"(c[1]), "f"(c[2]), "f"(c[3]));
}

// ---------------- tensor-core GEMM: C[M,128] = relu(A[M,K] @ B[128,K]^T + bias) ----
// 128x128 block tile, 8 warps (4Mx2N), warp tile 32x64, K chunked by 32.
// FUSE: A synthesized as [agg(prenormalized) | h_dst].  NORM: fused row L2 norm.
// HALF_OUT: write C as fp16 (for g_nh).
template<int K, bool FUSE, bool NORM, bool HALF_OUT>
__global__ void __launch_bounds__(256)
gemm_tc(const float* __restrict__ A,
        const float* __restrict__ hdst,
        const float* __restrict__ B,      // [128, K] row-major
        const float* __restrict__ bias,   // [128]
        void* __restrict__ Cv, int M)
{
    __shared__ uint32_t As[128][36];
    __shared__ uint32_t Bs[128][36];
    __shared__ float rowsq[128];
    __shared__ float rinv[128];

    const int t     = threadIdx.x;
    const int lane  = t & 31;
    const int w     = t >> 5;
    const int warpM = w >> 1;
    const int warpN = w & 1;
    const int row0  = blockIdx.x * 128;
    const int gid   = lane >> 2;
    const int tig   = lane & 3;

    float acc[2][8][4];
    #pragma unroll
    for (int mt = 0; mt < 2; mt++)
        #pragma unroll
        for (int nt = 0; nt < 8; nt++)
            #pragma unroll
            for (int r = 0; r < 4; r++) acc[mt][nt][r] = 0.f;

    for (int k0 = 0; k0 < K; k0 += 32) {
        #pragma unroll
        for (int i = 0; i < 4; i++) {
            int lin = t + i * 256;
            int row = lin >> 3;
            int q   = lin & 7;
            int kk  = k0 + q * 4;

            float4 va = make_float4(0.f, 0.f, 0.f, 0.f);
            int gr = row0 + row;
            if (gr < M) {
                if (FUSE) {
                    if (kk < 128)
                        va = *(const float4*)(A + (size_t)gr * 128 + kk);
                    else
                        va = *(const float4*)(hdst + (size_t)gr * 128 + (kk - 128));
                } else {
                    va = *(const float4*)(A + (size_t)gr * K + kk);
                }
            }
            As[row][q * 4 + 0] = f2tf32(va.x);
            As[row][q * 4 + 1] = f2tf32(va.y);
            As[row][q * 4 + 2] = f2tf32(va.z);
            As[row][q * 4 + 3] = f2tf32(va.w);

            float4 vb = *(const float4*)(B + (size_t)row * K + kk);
            Bs[row][q * 4 + 0] = f2tf32(vb.x);
            Bs[row][q * 4 + 1] = f2tf32(vb.y);
            Bs[row][q * 4 + 2] = f2tf32(vb.z);
            Bs[row][q * 4 + 3] = f2tf32(vb.w);
        }
        __syncthreads();

        #pragma unroll
        for (int ks = 0; ks < 4; ks++) {
            const int kk = ks * 8;
            uint32_t a[2][4], b[8][2];
            #pragma unroll
            for (int mt = 0; mt < 2; mt++) {
                int r = warpM * 32 + mt * 16 + gid;
                a[mt][0] = As[r][kk + tig];
                a[mt][1] = As[r + 8][kk + tig];
                a[mt][2] = As[r][kk + tig + 4];
                a[mt][3] = As[r + 8][kk + tig + 4];
            }
            #pragma unroll
            for (int nt = 0; nt < 8; nt++) {
                int n = warpN * 64 + nt * 8 + gid;
                b[nt][0] = Bs[n][kk + tig];
                b[nt][1] = Bs[n][kk + tig + 4];
            }
            #pragma unroll
            for (int mt = 0; mt < 2; mt++)
                #pragma unroll
                for (int nt = 0; nt < 8; nt++)
                    mma_tf32(acc[mt][nt], a[mt], b[nt], acc[mt][nt]);
        }
        __syncthreads();
    }

    #pragma unroll
    for (int nt = 0; nt < 8; nt++) {
        int cb = warpN * 64 + nt * 8 + 2 * tig;
        float b0 = __ldg(bias + cb);
        float b1 = __ldg(bias + cb + 1);
        #pragma unroll
        for (int mt = 0; mt < 2; mt++) {
            acc[mt][nt][0] = fmaxf(acc[mt][nt][0] + b0, 0.f);
            acc[mt][nt][1] = fmaxf(acc[mt][nt][1] + b1, 0.f);
            acc[mt][nt][2] = fmaxf(acc[mt][nt][2] + b0, 0.f);
            acc[mt][nt][3] = fmaxf(acc[mt][nt][3] + b1, 0.f);
        }
    }

    if (NORM) {
        float* C = (float*)Cv;
        if (t < 128) rowsq[t] = 0.f;
        __syncthreads();
        #pragma unroll
        for (int mt = 0; mt < 2; mt++) {
            float sA = 0.f, sB = 0.f;
            #pragma unroll
            for (int nt = 0; nt < 8; nt++) {
                sA = fmaf(acc[mt][nt][0], acc[mt][nt][0], sA);
                sA = fmaf(acc[mt][nt][1], acc[mt][nt][1], sA);
                sB = fmaf(acc[mt][nt][2], acc[mt][nt][2], sB);
                sB = fmaf(acc[mt][nt][3], acc[mt][nt][3], sB);
            }
            sA += __shfl_xor_sync(0xffffffffu, sA, 1);
            sA += __shfl_xor_sync(0xffffffffu, sA, 2);
            sB += __shfl_xor_sync(0xffffffffu, sB, 1);
            sB += __shfl_xor_sync(0xffffffffu, sB, 2);
            if (tig == 0) {
                int lr = warpM * 32 + mt * 16 + gid;
                atomicAdd(&rowsq[lr], sA);
                atomicAdd(&rowsq[lr + 8], sB);
            }
        }
        __syncthreads();
        if (t < 128) {
            float nrm = sqrtf(rowsq[t]);
            rinv[t] = (nrm > 0.f) ? (1.f / nrm) : 1.f;
        }
        __syncthreads();
        #pragma unroll
        for (int mt = 0; mt < 2; mt++) {
            int lrA = warpM * 32 + mt * 16 + gid;
            int rA  = row0 + lrA;
            float sa = rinv[lrA];
            float sb = rinv[lrA + 8];
            #pragma unroll
            for (int nt = 0; nt < 8; nt++) {
                int cb = warpN * 64 + nt * 8 + 2 * tig;
                if (rA < M) {
                    float2 v = make_float2(acc[mt][nt][0] * sa, acc[mt][nt][1] * sa);
                    *(float2*)(C + (size_t)rA * 128 + cb) = v;
                }
                if (rA + 8 < M) {
                    float2 v = make_float2(acc[mt][nt][2] * sb, acc[mt][nt][3] * sb);
                    *(float2*)(C + (size_t)(rA + 8) * 128 + cb) = v;
                }
            }
        }
    } else {
        #pragma unroll
        for (int mt = 0; mt < 2; mt++) {
            int rA = row0 + warpM * 32 + mt * 16 + gid;
            #pragma unroll
            for (int nt = 0; nt < 8; nt++) {
                int cb = warpN * 64 + nt * 8 + 2 * tig;
                if (HALF_OUT) {
                    __half* C = (__half*)Cv;
                    if (rA < M) {
                        __half2 v = __floats2half2_rn(acc[mt][nt][0], acc[mt][nt][1]);
                        *(__half2*)(C + (size_t)rA * 128 + cb) = v;
                    }
                    if (rA + 8 < M) {
                        __half2 v = __floats2half2_rn(acc[mt][nt][2], acc[mt][nt][3]);
                        *(__half2*)(C + (size_t)(rA + 8) * 128 + cb) = v;
                    }
                } else {
                    float* C = (float*)Cv;
                    if (rA < M) {
                        float2 v = make_float2(acc[mt][nt][0], acc[mt][nt][1]);
                        *(float2*)(C + (size_t)rA * 128 + cb) = v;
                    }
                    if (rA + 8 < M) {
                        float2 v = make_float2(acc[mt][nt][2], acc[mt][nt][3]);
                        *(float2*)(C + (size_t)(rA + 8) * 128 + cb) = v;
                    }
                }
            }
        }
    }
}

// ---------------- CSR build ----------------
__global__ void __launch_bounds__(256)
hist_kernel(const int* __restrict__ dst)
{
    int e = blockIdx.x * 256 + threadIdx.x;
    if (e < NE) atomicAdd(&g_deg[dst[e]], 1);
}

__global__ void __launch_bounds__(256)
scan_kernel()
{
    __shared__ int s[256];
    __shared__ int base;
    int d = blockIdx.x * 256 + threadIdx.x;
    int t = threadIdx.x;
    int deg = (d < N_DST) ? g_deg[d] : 0;
    s[t] = deg;
    __syncthreads();
    #pragma unroll
    for (int o = 1; o < 256; o <<= 1) {
        int v = (t >= o) ? s[t - o] : 0;
        __syncthreads();
        s[t] += v;
        __syncthreads();
    }
    if (t == 255) base = atomicAdd(&g_total, s[255]);
    __syncthreads();
    if (d < N_DST) {
        int off = base + s[t] - deg;   // exclusive
        g_off[d] = off;
        g_cur[d] = off;
    }
}

__global__ void __launch_bounds__(256)
bucket_kernel(const int* __restrict__ src,
              const int* __restrict__ dst,
              const float* __restrict__ w)
{
    int e = blockIdx.x * 256 + threadIdx.x;
    if (e >= NE) return;
    int d = dst[e];
    int pos = atomicAdd(&g_cur[d], 1);
    uint32_t wb = __float_as_uint(w[e]);
    g_edge[pos] = (uint64_t)(uint32_t)src[e] | ((uint64_t)wb << 32);
}

// ---------------- aggregation: warp per dst node, no atomics, fp16 gather -------
__global__ void __launch_bounds__(256)
aggregate_kernel()
{
    int d = blockIdx.x * 8 + (threadIdx.x >> 5);
    if (d >= N_DST) return;
    int lane = threadIdx.x & 31;
    int beg = g_off[d];
    int end = g_cur[d];

    float4 acc = make_float4(0.f, 0.f, 0.f, 0.f);
    float ws = 0.f;
    int i = beg;
    // 4-wide software pipeline: keep 4 row-gathers in flight
    for (; i + 3 < end; i += 4) {
        uint64_t e0 = g_edge[i],     e1 = g_edge[i + 1];
        uint64_t e2 = g_edge[i + 2], e3 = g_edge[i + 3];
        int   s0 = (int)(uint32_t)e0, s1 = (int)(uint32_t)e1;
        int   s2 = (int)(uint32_t)e2, s3 = (int)(uint32_t)e3;
        float w0 = __uint_as_float((uint32_t)(e0 >> 32));
        float w1 = __uint_as_float((uint32_t)(e1 >> 32));
        float w2 = __uint_as_float((uint32_t)(e2 >> 32));
        float w3 = __uint_as_float((uint32_t)(e3 >> 32));
        uint2 r0 = ((const uint2*)(g_nh + (size_t)s0 * 128))[lane];
        uint2 r1 = ((const uint2*)(g_nh + (size_t)s1 * 128))[lane];
        uint2 r2 = ((const uint2*)(g_nh + (size_t)s2 * 128))[lane];
        uint2 r3 = ((const uint2*)(g_nh + (size_t)s3 * 128))[lane];
        float2 a0 = __half22float2(*(__half2*)&r0.x), b0 = __half22float2(*(__half2*)&r0.y);
        float2 a1 = __half22float2(*(__half2*)&r1.x), b1 = __half22float2(*(__half2*)&r1.y);
        float2 a2 = __half22float2(*(__half2*)&r2.x), b2 = __half22float2(*(__half2*)&r2.y);
        float2 a3 = __half22float2(*(__half2*)&r3.x), b3 = __half22float2(*(__half2*)&r3.y);
        acc.x = fmaf(a0.x, w0, acc.x); acc.y = fmaf(a0.y, w0, acc.y);
        acc.z = fmaf(b0.x, w0, acc.z); acc.w = fmaf(b0.y, w0, acc.w);
        acc.x = fmaf(a1.x, w1, acc.x); acc.y = fmaf(a1.y, w1, acc.y);
        acc.z = fmaf(b1.x, w1, acc.z); acc.w = fmaf(b1.y, w1, acc.w);
        acc.x = fmaf(a2.x, w2, acc.x); acc.y = fmaf(a2.y, w2, acc.y);
        acc.z = fmaf(b2.x, w2, acc.z); acc.w = fmaf(b2.y, w2, acc.w);
        acc.x = fmaf(a3.x, w3, acc.x); acc.y = fmaf(a3.y, w3, acc.y);
        acc.z = fmaf(b3.x, w3, acc.z); acc.w = fmaf(b3.y, w3, acc.w);
        ws += (w0 + w1) + (w2 + w3);
    }
    for (; i < end; i++) {
        uint64_t e0 = g_edge[i];
        int   s0 = (int)(uint32_t)e0;
        float w0 = __uint_as_float((uint32_t)(e0 >> 32));
        uint2 r0 = ((const uint2*)(g_nh + (size_t)s0 * 128))[lane];
        float2 a0 = __half22float2(*(__half2*)&r0.x), b0 = __half22float2(*(__half2*)&r0.y);
        acc.x = fmaf(a0.x, w0, acc.x); acc.y = fmaf(a0.y, w0, acc.y);
        acc.z = fmaf(b0.x, w0, acc.z); acc.w = fmaf(b0.y, w0, acc.w);
        ws += w0;
    }
    float inv = 1.f / fmaxf(ws, 1.f);
    acc.x *= inv; acc.y *= inv; acc.z *= inv; acc.w *= inv;
    ((float4*)(g_agg + (size_t)d * 128))[lane] = acc;
}

extern "C" void kernel_launch(void* const* d_in, const int* in_sizes, int n_in,
                              void* d_out, int out_size)
{
    const float* h_src   = (const float*)d_in[0];
    const float* h_dst   = (const float*)d_in[1];
    const float* weights = (const float*)d_in[2];
    const float* Qw      = (const float*)d_in[3];
    const float* Qb      = (const float*)d_in[4];
    const float* Ww      = (const float*)d_in[5];
    const float* Wb      = (const float*)d_in[6];
    const int*   src     = (const int*)d_in[7];
    const int*   dst     = (const int*)d_in[8];
    float*       out     = (float*)d_out;

    static void *p_nh = nullptr;
    static float *p_agg = nullptr;
    static int   *p_deg = nullptr, *p_total = nullptr;
    if (!p_nh) {
        cudaGetSymbolAddress(&p_nh,            g_nh);
        cudaGetSymbolAddress((void**)&p_agg,   g_agg);
        cudaGetSymbolAddress((void**)&p_deg,   g_deg);
        cudaGetSymbolAddress((void**)&p_total, g_total);
    }

    // 0) reset CSR counters
    cudaMemsetAsync(p_deg,   0, N_DST * sizeof(int));
    cudaMemsetAsync(p_total, 0, sizeof(int));

    // 1) n = relu(h_src @ Q^T + Qb)   [tf32 tensor cores, fp16 output]
    gemm_tc<128, false, false, true><<<(N_SRC + 127) / 128, 256>>>(
        h_src, nullptr, Qw, Qb, p_nh, N_SRC);

    // 2) CSR build
    hist_kernel<<<(NE + 255) / 256, 256>>>(dst);
    scan_kernel<<<(N_DST + 255) / 256, 256>>>();
    bucket_kernel<<<(NE + 255) / 256, 256>>>(src, dst, weights);

    // 3) aggregate (atomic-free, pre-normalized, fp16 gather)
    aggregate_kernel<<<(N_DST + 7) / 8, 256>>>();

    // 4) out = L2norm(relu([agg , h_dst] @ W^T + Wb))   [tf32 tensor cores]
    gemm_tc<256, true, true, false><<<(N_DST + 127) / 128, 256>>>(
        p_agg, h_dst, Ww, Wb, out, N_DST);
}

// round 6
// speedup vs baseline: 3.9271x; 1.0928x over previous
#include <cuda_runtime.h>
#include <cuda_fp16.h>
#include <math.h>
#include <stdint.h>

#define N_SRC 100000
#define N_DST 100000
#define NE    1600000
#define DIN   128
#define DOUT  128

// ---------------- scratch (static device globals; no allocs allowed) ----------------
__device__ __half    g_nh[(size_t)N_SRC * DOUT];  // relu(h_src @ Q^T + b), fp16
__device__ float     g_agg[(size_t)N_DST * DOUT]; // aggregated + normalized messages
__device__ int       g_deg[N_DST];                // per-dst degree
__device__ int       g_off[N_DST];                // CSR bucket start
__device__ int       g_cur[N_DST];                // CSR cursor (== end after fill)
__device__ uint64_t  g_edge[NE];                  // packed (src:int32 lo, w:f32 hi)
__device__ int       g_total;                     // global scan counter

// ---------------- fp16 MMA helpers ----------------
__device__ __forceinline__ uint32_t pack_h2(float x, float y) {
    __half2 h = __floats2half2_rn(x, y);
    return *(uint32_t*)&h;
}

__device__ __forceinline__ void mma_f16(float* d, const uint32_t* a,
                                        const uint32_t* b, const float* c) {
    asm volatile(
        "mma.sync.aligned.m16n8k16.row.col.f32.f16.f16.f32 "
        "{%0,%1,%2,%3}, {%4,%5,%6,%7}, {%8,%9}, {%10,%11,%12,%13};\n"
        : "=f"(d[0]), "=f"(d[1]), "=f"(d[2]), "=f"(d[3])
        : "r"(a[0]), "r"(a[1]), "r"(a[2]), "r"(a[3]),
          "r"(b[0]), "r"(b[1]),
          "f"(c[0]), "f"(c[1]), "f"(c[2]), "f"(c[3]));
}

// ---------------- tensor-core GEMM: C[M,128] = relu(A[M,K] @ B[128,K]^T + bias) ----
// 128x128 block tile, 8 warps (4Mx2N), warp tile 32x64, K chunked by 32 halves.
// fp16 mma m16n8k16, fp32 accumulate. Smem stride 20 words (conflict-free).
// FUSE: A synthesized as [agg(prenormalized) | h_dst].  NORM: fused row L2 norm.
// HALF_OUT: write C as fp16 (for g_nh).
template<int K, bool FUSE, bool NORM, bool HALF_OUT>
__global__ void __launch_bounds__(256)
gemm_tc(const float* __restrict__ A,
        const float* __restrict__ hdst,
        const float* __restrict__ B,      // [128, K] row-major fp32
        const float* __restrict__ bias,   // [128]
        void* __restrict__ Cv, int M)
{
    __shared__ uint32_t As[128][20];   // 16 half2 words + pad 4
    __shared__ uint32_t Bs[128][20];
    __shared__ float rowsq[128];
    __shared__ float rinv[128];

    const int t     = threadIdx.x;
    const int lane  = t & 31;
    const int w     = t >> 5;
    const int warpM = w >> 1;
    const int warpN = w & 1;
    const int row0  = blockIdx.x * 128;
    const int gid   = lane >> 2;
    const int tig   = lane & 3;

    float acc[2][8][4];
    #pragma unroll
    for (int mt = 0; mt < 2; mt++)
        #pragma unroll
        for (int nt = 0; nt < 8; nt++)
            #pragma unroll
            for (int r = 0; r < 4; r++) acc[mt][nt][r] = 0.f;

    for (int k0 = 0; k0 < K; k0 += 32) {
        // ---- stage chunk: fp32 global -> fp16 smem ----
        #pragma unroll
        for (int i = 0; i < 4; i++) {
            int lin = t + i * 256;        // 0..1023
            int row = lin >> 3;           // 0..127
            int q   = lin & 7;            // float4 slot (4 floats)
            int kk  = k0 + q * 4;

            float4 va = make_float4(0.f, 0.f, 0.f, 0.f);
            int gr = row0 + row;
            if (gr < M) {
                if (FUSE) {
                    if (kk < 128)
                        va = *(const float4*)(A + (size_t)gr * 128 + kk);
                    else
                        va = *(const float4*)(hdst + (size_t)gr * 128 + (kk - 128));
                } else {
                    va = *(const float4*)(A + (size_t)gr * K + kk);
                }
            }
            As[row][q * 2 + 0] = pack_h2(va.x, va.y);
            As[row][q * 2 + 1] = pack_h2(va.z, va.w);

            float4 vb = *(const float4*)(B + (size_t)row * K + kk);
            Bs[row][q * 2 + 0] = pack_h2(vb.x, vb.y);
            Bs[row][q * 2 + 1] = pack_h2(vb.z, vb.w);
        }
        __syncthreads();

        // ---- 2 k-steps of 16 ----
        #pragma unroll
        for (int ks = 0; ks < 2; ks++) {
            const int kk = ks * 8;        // word offset
            uint32_t a[2][4], b[8][2];
            #pragma unroll
            for (int mt = 0; mt < 2; mt++) {
                int r = warpM * 32 + mt * 16 + gid;
                a[mt][0] = As[r][kk + tig];
                a[mt][1] = As[r + 8][kk + tig];
                a[mt][2] = As[r][kk + tig + 4];
                a[mt][3] = As[r + 8][kk + tig + 4];
            }
            #pragma unroll
            for (int nt = 0; nt < 8; nt++) {
                int n = warpN * 64 + nt * 8 + gid;
                b[nt][0] = Bs[n][kk + tig];
                b[nt][1] = Bs[n][kk + tig + 4];
            }
            #pragma unroll
            for (int mt = 0; mt < 2; mt++)
                #pragma unroll
                for (int nt = 0; nt < 8; nt++)
                    mma_f16(acc[mt][nt], a[mt], b[nt], acc[mt][nt]);
        }
        __syncthreads();
    }

    // ---- epilogue: bias + relu ----
    #pragma unroll
    for (int nt = 0; nt < 8; nt++) {
        int cb = warpN * 64 + nt * 8 + 2 * tig;
        float b0 = __ldg(bias + cb);
        float b1 = __ldg(bias + cb + 1);
        #pragma unroll
        for (int mt = 0; mt < 2; mt++) {
            acc[mt][nt][0] = fmaxf(acc[mt][nt][0] + b0, 0.f);
            acc[mt][nt][1] = fmaxf(acc[mt][nt][1] + b1, 0.f);
            acc[mt][nt][2] = fmaxf(acc[mt][nt][2] + b0, 0.f);
            acc[mt][nt][3] = fmaxf(acc[mt][nt][3] + b1, 0.f);
        }
    }

    if (NORM) {
        float* C = (float*)Cv;
        if (t < 128) rowsq[t] = 0.f;
        __syncthreads();
        #pragma unroll
        for (int mt = 0; mt < 2; mt++) {
            float sA = 0.f, sB = 0.f;
            #pragma unroll
            for (int nt = 0; nt < 8; nt++) {
                sA = fmaf(acc[mt][nt][0], acc[mt][nt][0], sA);
                sA = fmaf(acc[mt][nt][1], acc[mt][nt][1], sA);
                sB = fmaf(acc[mt][nt][2], acc[mt][nt][2], sB);
                sB = fmaf(acc[mt][nt][3], acc[mt][nt][3], sB);
            }
            sA += __shfl_xor_sync(0xffffffffu, sA, 1);
            sA += __shfl_xor_sync(0xffffffffu, sA, 2);
            sB += __shfl_xor_sync(0xffffffffu, sB, 1);
            sB += __shfl_xor_sync(0xffffffffu, sB, 2);
            if (tig == 0) {
                int lr = warpM * 32 + mt * 16 + gid;
                atomicAdd(&rowsq[lr], sA);
                atomicAdd(&rowsq[lr + 8], sB);
            }
        }
        __syncthreads();
        if (t < 128) {
            float nrm = sqrtf(rowsq[t]);
            rinv[t] = (nrm > 0.f) ? (1.f / nrm) : 1.f;
        }
        __syncthreads();
        #pragma unroll
        for (int mt = 0; mt < 2; mt++) {
            int lrA = warpM * 32 + mt * 16 + gid;
            int rA  = row0 + lrA;
            float sa = rinv[lrA];
            float sb = rinv[lrA + 8];
            #pragma unroll
            for (int nt = 0; nt < 8; nt++) {
                int cb = warpN * 64 + nt * 8 + 2 * tig;
                if (rA < M) {
                    float2 v = make_float2(acc[mt][nt][0] * sa, acc[mt][nt][1] * sa);
                    *(float2*)(C + (size_t)rA * 128 + cb) = v;
                }
                if (rA + 8 < M) {
                    float2 v = make_float2(acc[mt][nt][2] * sb, acc[mt][nt][3] * sb);
                    *(float2*)(C + (size_t)(rA + 8) * 128 + cb) = v;
                }
            }
        }
    } else {
        #pragma unroll
        for (int mt = 0; mt < 2; mt++) {
            int rA = row0 + warpM * 32 + mt * 16 + gid;
            #pragma unroll
            for (int nt = 0; nt < 8; nt++) {
                int cb = warpN * 64 + nt * 8 + 2 * tig;
                if (HALF_OUT) {
                    __half* C = (__half*)Cv;
                    if (rA < M) {
                        __half2 v = __floats2half2_rn(acc[mt][nt][0], acc[mt][nt][1]);
                        *(__half2*)(C + (size_t)rA * 128 + cb) = v;
                    }
                    if (rA + 8 < M) {
                        __half2 v = __floats2half2_rn(acc[mt][nt][2], acc[mt][nt][3]);
                        *(__half2*)(C + (size_t)(rA + 8) * 128 + cb) = v;
                    }
                } else {
                    float* C = (float*)Cv;
                    if (rA < M) {
                        float2 v = make_float2(acc[mt][nt][0], acc[mt][nt][1]);
                        *(float2*)(C + (size_t)rA * 128 + cb) = v;
                    }
                    if (rA + 8 < M) {
                        float2 v = make_float2(acc[mt][nt][2], acc[mt][nt][3]);
                        *(float2*)(C + (size_t)(rA + 8) * 128 + cb) = v;
                    }
                }
            }
        }
    }
}

// ---------------- CSR build ----------------
__global__ void __launch_bounds__(256)
hist_kernel(const int* __restrict__ dst)
{
    int e = blockIdx.x * 256 + threadIdx.x;
    if (e < NE) atomicAdd(&g_deg[dst[e]], 1);
}

__global__ void __launch_bounds__(256)
scan_kernel()
{
    __shared__ int s[256];
    __shared__ int base;
    int d = blockIdx.x * 256 + threadIdx.x;
    int t = threadIdx.x;
    int deg = (d < N_DST) ? g_deg[d] : 0;
    s[t] = deg;
    __syncthreads();
    #pragma unroll
    for (int o = 1; o < 256; o <<= 1) {
        int v = (t >= o) ? s[t - o] : 0;
        __syncthreads();
        s[t] += v;
        __syncthreads();
    }
    if (t == 255) base = atomicAdd(&g_total, s[255]);
    __syncthreads();
    if (d < N_DST) {
        int off = base + s[t] - deg;   // exclusive
        g_off[d] = off;
        g_cur[d] = off;
    }
}

__global__ void __launch_bounds__(256)
bucket_kernel(const int* __restrict__ src,
              const int* __restrict__ dst,
              const float* __restrict__ w)
{
    int e = blockIdx.x * 256 + threadIdx.x;
    if (e >= NE) return;
    int d = dst[e];
    int pos = atomicAdd(&g_cur[d], 1);
    uint32_t wb = __float_as_uint(w[e]);
    g_edge[pos] = (uint64_t)(uint32_t)src[e] | ((uint64_t)wb << 32);
}

// ---------------- aggregation: warp per dst node, no atomics, fp16 gather -------
__global__ void __launch_bounds__(256)
aggregate_kernel()
{
    int d = blockIdx.x * 8 + (threadIdx.x >> 5);
    if (d >= N_DST) return;
    int lane = threadIdx.x & 31;
    int beg = g_off[d];
    int end = g_cur[d];

    float4 acc = make_float4(0.f, 0.f, 0.f, 0.f);
    float ws = 0.f;
    int i = beg;
    for (; i + 3 < end; i += 4) {
        uint64_t e0 = g_edge[i],     e1 = g_edge[i + 1];
        uint64_t e2 = g_edge[i + 2], e3 = g_edge[i + 3];
        int   s0 = (int)(uint32_t)e0, s1 = (int)(uint32_t)e1;
        int   s2 = (int)(uint32_t)e2, s3 = (int)(uint32_t)e3;
        float w0 = __uint_as_float((uint32_t)(e0 >> 32));
        float w1 = __uint_as_float((uint32_t)(e1 >> 32));
        float w2 = __uint_as_float((uint32_t)(e2 >> 32));
        float w3 = __uint_as_float((uint32_t)(e3 >> 32));
        uint2 r0 = ((const uint2*)(g_nh + (size_t)s0 * 128))[lane];
        uint2 r1 = ((const uint2*)(g_nh + (size_t)s1 * 128))[lane];
        uint2 r2 = ((const uint2*)(g_nh + (size_t)s2 * 128))[lane];
        uint2 r3 = ((const uint2*)(g_nh + (size_t)s3 * 128))[lane];
        float2 a0 = __half22float2(*(__half2*)&r0.x), b0 = __half22float2(*(__half2*)&r0.y);
        float2 a1 = __half22float2(*(__half2*)&r1.x), b1 = __half22float2(*(__half2*)&r1.y);
        float2 a2 = __half22float2(*(__half2*)&r2.x), b2 = __half22float2(*(__half2*)&r2.y);
        float2 a3 = __half22float2(*(__half2*)&r3.x), b3 = __half22float2(*(__half2*)&r3.y);
        acc.x = fmaf(a0.x, w0, acc.x); acc.y = fmaf(a0.y, w0, acc.y);
        acc.z = fmaf(b0.x, w0, acc.z); acc.w = fmaf(b0.y, w0, acc.w);
        acc.x = fmaf(a1.x, w1, acc.x); acc.y = fmaf(a1.y, w1, acc.y);
        acc.z = fmaf(b1.x, w1, acc.z); acc.w = fmaf(b1.y, w1, acc.w);
        acc.x = fmaf(a2.x, w2, acc.x); acc.y = fmaf(a2.y, w2, acc.y);
        acc.z = fmaf(b2.x, w2, acc.z); acc.w = fmaf(b2.y, w2, acc.w);
        acc.x = fmaf(a3.x, w3, acc.x); acc.y = fmaf(a3.y, w3, acc.y);
        acc.z = fmaf(b3.x, w3, acc.z); acc.w = fmaf(b3.y, w3, acc.w);
        ws += (w0 + w1) + (w2 + w3);
    }
    for (; i < end; i++) {
        uint64_t e0 = g_edge[i];
        int   s0 = (int)(uint32_t)e0;
        float w0 = __uint_as_float((uint32_t)(e0 >> 32));
        uint2 r0 = ((const uint2*)(g_nh + (size_t)s0 * 128))[lane];
        float2 a0 = __half22float2(*(__half2*)&r0.x), b0 = __half22float2(*(__half2*)&r0.y);
        acc.x = fmaf(a0.x, w0, acc.x); acc.y = fmaf(a0.y, w0, acc.y);
        acc.z = fmaf(b0.x, w0, acc.z); acc.w = fmaf(b0.y, w0, acc.w);
        ws += w0;
    }
    float inv = 1.f / fmaxf(ws, 1.f);
    acc.x *= inv; acc.y *= inv; acc.z *= inv; acc.w *= inv;
    ((float4*)(g_agg + (size_t)d * 128))[lane] = acc;
}

extern "C" void kernel_launch(void* const* d_in, const int* in_sizes, int n_in,
                              void* d_out, int out_size)
{
    const float* h_src   = (const float*)d_in[0];
    const float* h_dst   = (const float*)d_in[1];
    const float* weights = (const float*)d_in[2];
    const float* Qw      = (const float*)d_in[3];
    const float* Qb      = (const float*)d_in[4];
    const float* Ww      = (const float*)d_in[5];
    const float* Wb      = (const float*)d_in[6];
    const int*   src     = (const int*)d_in[7];
    const int*   dst     = (const int*)d_in[8];
    float*       out     = (float*)d_out;

    static void *p_nh = nullptr;
    static float *p_agg = nullptr;
    static int   *p_deg = nullptr, *p_total = nullptr;
    if (!p_nh) {
        cudaGetSymbolAddress(&p_nh,            g_nh);
        cudaGetSymbolAddress((void**)&p_agg,   g_agg);
        cudaGetSymbolAddress((void**)&p_deg,   g_deg);
        cudaGetSymbolAddress((void**)&p_total, g_total);
    }

    // 0) reset CSR counters
    cudaMemsetAsync(p_deg,   0, N_DST * sizeof(int));
    cudaMemsetAsync(p_total, 0, sizeof(int));

    // 1) n = relu(h_src @ Q^T + Qb)   [fp16 tensor cores, fp16 output]
    gemm_tc<128, false, false, true><<<(N_SRC + 127) / 128, 256>>>(
        h_src, nullptr, Qw, Qb, p_nh, N_SRC);

    // 2) CSR build
    hist_kernel<<<(NE + 255) / 256, 256>>>(dst);
    scan_kernel<<<(N_DST + 255) / 256, 256>>>();
    bucket_kernel<<<(NE + 255) / 256, 256>>>(src, dst, weights);

    // 3) aggregate (atomic-free, pre-normalized, fp16 gather)
    aggregate_kernel<<<(N_DST + 7) / 8, 256>>>();

    // 4) out = L2norm(relu([agg , h_dst] @ W^T + Wb))   [fp16 tensor cores]
    gemm_tc<256, true, true, false><<<(N_DST + 127) / 128, 256>>>(
        p_agg, h_dst, Ww, Wb, out, N_DST);
}